// round 6
// baseline (speedup 1.0000x reference)
#include <cuda_runtime.h>

#define BB 4
#define XX 96
#define XYZ (XX*XX*XX)          // 884736
#define G 192
#define GW (G*G*G/32)           // 221184 words per batch
#define NROW (BB*XX*XX)         // 36864 (b,x,y) rows
#define NPACK (NROW*3)          // packed words

// ---------------- device scratch (no allocations allowed) ----------------
__device__ float g_minvox[BB][3];
__device__ float g_posbase[BB][3];
__device__ float g_voxsize[BB][3];
__device__ float g_sizevox[3];
__device__ __align__(16) unsigned g_occ[BB][GW];   // 3.54 MB occupancy bitmap
__device__ __align__(16) unsigned g_pack[NPACK];   // sampled grid, bit-packed along z
__device__ __align__(16) unsigned g_rand[NPACK];   // rand_idx overlay bits
// per-axis trilinear tables: [b*3+c][i]  (c=0:x premul*1152, c=1:y premul*6, c=2:z raw)
__device__ int g_tA[BB*3][XX];
__device__ int g_tB[BB*3][XX];
__device__ int g_tU[BB*3][XX];

// ---------------- K1: init = clear bitmaps + setup math + tables ----------------
__global__ void k_init(const float* __restrict__ coords,
                       const float* __restrict__ T,
                       const float* __restrict__ Tinv) {
    if (blockIdx.x != 0) {
        // clearing blocks
        int nthr = (gridDim.x - 1) * blockDim.x;
        int t = (blockIdx.x - 1) * blockDim.x + threadIdx.x;
        uint4 z4 = make_uint4(0, 0, 0, 0);
        uint4* o4 = (uint4*)g_occ;
        for (int i = t; i < BB * GW / 4; i += nthr) o4[i] = z4;
        uint4* r4 = (uint4*)g_rand;
        for (int i = t; i < NPACK / 4; i += nthr) r4[i] = z4;
        return;
    }
    // block 0: setup
    if (threadIdx.x == 0) {
        float minl[BB][3], maxl[BB][3];
        for (int b = 0; b < BB; b++)
            for (int c = 0; c < 3; c++) {
                float v0 = coords[(size_t)(b * 3 + c) * XYZ];
                float v1 = coords[(size_t)(b * 3 + c) * XYZ + (XYZ - 1)];
                minl[b][c] = fminf(v0, v1);
                maxl[b][c] = fmaxf(v0, v1);
            }
        float msg[3];
        for (int c = 0; c < 3; c++) {
            float m = -3.402823466e38f;
            for (int b = 0; b < BB; b++)
                m = fmaxf(m, (maxl[b][c] + 0.08f) - minl[b][c]);
            msg[c] = m;
        }
        float mv[BB][3];
        for (int b = 0; b < BB; b++) {
            float mh[4] = {minl[b][0], minl[b][1], minl[b][2], 1.0f};
            for (int i = 0; i < 3; i++) {
                float s = 0.0f;
                for (int j = 0; j < 4; j++) s += Tinv[b * 16 + i * 4 + j] * mh[j];
                float v = fmaxf(floorf(s), 0.0f);
                mv[b][i] = v;
                g_minvox[b][i] = v;
            }
        }
        float sv[3];
        for (int i = 0; i < 3; i++) {
            float m = -3.402823466e38f;
            for (int b = 0; b < BB; b++) {
                float s = 0.0f;
                for (int j = 0; j < 3; j++) s += Tinv[b * 16 + i * 4 + j] * msg[j];
                m = fmaxf(m, s);
            }
            sv[i] = ceilf(m);
            g_sizevox[i] = sv[i];
        }
        for (int b = 0; b < BB; b++) {
            float mh[4] = {mv[b][0], mv[b][1], mv[b][2], 1.0f};
            for (int i = 0; i < 3; i++) {
                float s = 0.0f;
                for (int j = 0; j < 4; j++) s += T[b * 16 + i * 4 + j] * mh[j];
                g_posbase[b][i] = s;
                float e = 0.0f;
                for (int j = 0; j < 3; j++) e += T[b * 16 + i * 4 + j] * sv[j];
                g_voxsize[b][i] = e / sv[i];
            }
        }
    }
    __syncthreads();
    for (int t = threadIdx.x; t < BB * 3 * XX; t += blockDim.x) {
        int i  = t % XX;
        int ch = t / XX;          // b*3+c
        int b  = ch / 3;
        int c  = ch - b * 3;
        float off = coords[(size_t)ch * XYZ];
        float val = (float)i * 0.08f + off;              // bit-exact meshgrid value
        float p  = (val - g_posbase[b][c]) / g_voxsize[b][c] - 0.5f;
        float p0 = floorf(p);
        float f  = p - p0;
        int ip = (int)p0;
        int i0 = min(max(ip, 0), G - 1);
        int i1 = min(max(ip + 1, 0), G - 1);
        int mul = (c == 0) ? 1152 : (c == 1) ? 6 : 1;
        g_tA[ch][i] = i0 * mul;
        g_tB[ch][i] = i1 * mul;
        g_tU[ch][i] = (f > 0.0f) ? 1 : 0;
    }
}

// ---------------- K2: scatter sparse points + rand overlay ----------------
__global__ void k_scatter(const int* __restrict__ sparse, int npts, int nperb,
                          const int* __restrict__ ridx, int na, int sb) {
    if ((int)blockIdx.x >= sb) {
        // rand overlay: bit-scatter into g_rand
        int i = (blockIdx.x - sb) * blockDim.x + threadIdx.x;
        if (i >= na) return;
        int b = i % BB;
        int x = ridx[i];
        int y = ridx[na + i];
        int z = ridx[2 * na + i];
        int p = (b * XX + x) * XX + y;
        atomicOr(&g_rand[p * 3 + (z >> 5)], 1u << (z & 31));
        return;
    }
    int t = blockIdx.x * blockDim.x + threadIdx.x;
    int p0 = t * 4;
    if (p0 >= npts) return;
    const int4* s4 = (const int4*)(sparse + (size_t)p0 * 3);
    int4 a = s4[0], bq = s4[1], cq = s4[2];
    int pts[4][3] = {{a.x, a.y, a.z}, {a.w, bq.x, bq.y},
                     {bq.z, bq.w, cq.x}, {cq.y, cq.z, cq.w}};
    int sv0 = (int)g_sizevox[0], sv1 = (int)g_sizevox[1], sv2 = (int)g_sizevox[2];
    int b = p0 / nperb;   // nperb % 4 == 0 -> all 4 points same batch
    int m0 = (int)g_minvox[b][0], m1 = (int)g_minvox[b][1], m2 = (int)g_minvox[b][2];
    unsigned* occ = g_occ[b];
#pragma unroll
    for (int i = 0; i < 4; i++) {
        if (p0 + i >= npts) return;
        int se0 = pts[i][0] - m0;
        int se1 = pts[i][1] - m1;
        int se2 = pts[i][2] - m2;
        if (se0 < 0 || se0 >= sv0 || se1 < 0 || se1 >= sv1 || se2 < 0 || se2 >= sv2)
            continue;
        int id = (min(se0, G - 1) * G + min(se1, G - 1)) * G + min(se2, G - 1);
        atomicOr(&occ[id >> 5], 1u << (id & 31));
    }
}

// ---------------- K3: table-driven boolean trilinear sample ----------------
__global__ void k_sample(float* __restrict__ occ_out) {
    int v = blockIdx.x * blockDim.x + threadIdx.x;   // grid sized exactly BB*XYZ
    int b = v / XYZ;
    int r = v - b * XYZ;
    int z = r % XX;
    int y = (r / XX) % XX;
    int x = r / (XX * XX);
    int bc = b * 3;
    int wx0 = g_tA[bc][x],     wx1 = g_tB[bc][x];     bool ux = g_tU[bc][x];
    int wy0 = g_tA[bc + 1][y], wy1 = g_tB[bc + 1][y]; bool uy = g_tU[bc + 1][y];
    int iz0 = g_tA[bc + 2][z], iz1 = g_tB[bc + 2][z]; bool uz = g_tU[bc + 2][z];
    const unsigned* occ = g_occ[b];
    int zw0 = iz0 >> 5; unsigned mz0 = 1u << (iz0 & 31);
    int zw1 = iz1 >> 5; unsigned mz1 = 1u << (iz1 & 31);
    bool samew = (zw1 == zw0);
    unsigned acc = 0;
#define PROBE(base) do {                                             \
        unsigned w0 = occ[(base) + zw0];                             \
        acc |= w0 & mz0;                                             \
        if (uz) {                                                    \
            unsigned w1 = samew ? w0 : occ[(base) + zw1];            \
            acc |= w1 & mz1;                                         \
        }                                                            \
    } while (0)
    PROBE(wx0 + wy0);
    if (uy) PROBE(wx0 + wy1);
    if (ux) {
        PROBE(wx1 + wy0);
        if (uy) PROBE(wx1 + wy1);
    }
#undef PROBE
    bool any = acc != 0;
    occ_out[v] = any ? 1.0f : 0.0f;
    unsigned w = __ballot_sync(0xFFFFFFFFu, any);
    if ((v & 31) == 0) g_pack[v >> 5] = w;
}

// ---------------- K4: fused 5x5x5 dilation (smem-tiled) + rand OR + expand ----------------
// Block = (batch, y-slab of 6). 576 threads: (x=tid%96, yo=tid/96). 64 blocks.
#define YS 6
__global__ void __launch_bounds__(XX*YS) k_dilate(float* __restrict__ mask) {
    __shared__ unsigned sp[YS + 4][XX][3];    // pack halo tile (y0-2 .. y0+YS+1)
    __shared__ unsigned ryz[YS][XX][3];       // after y+z dilation
    int b  = blockIdx.x / (XX / YS);
    int y0 = (blockIdx.x % (XX / YS)) * YS;
    int tid = threadIdx.x;
    // load halo tile
    for (int i = tid; i < (YS + 4) * XX * 3; i += XX * YS) {
        int yy = i / (XX * 3);
        int rem = i - yy * (XX * 3);
        int x = rem / 3;
        int k = rem - x * 3;
        int y = y0 - 2 + yy;
        unsigned vw = 0;
        if (y >= 0 && y < XX)
            vw = g_pack[((b * XX + x) * XX + y) * 3 + k];
        sp[yy][x][k] = vw;
    }
    __syncthreads();
    int x  = tid % XX;
    int yo = tid / XX;
    {
        unsigned a0 = 0, a1 = 0, a2 = 0;
#pragma unroll
        for (int dy = 0; dy < 5; dy++) {
            a0 |= sp[yo + dy][x][0];
            a1 |= sp[yo + dy][x][1];
            a2 |= sp[yo + dy][x][2];
        }
        ryz[yo][x][0] = a0 | (a0 << 1) | (a0 << 2) | (a0 >> 1) | (a0 >> 2)
                      | (a1 << 31) | (a1 << 30);
        ryz[yo][x][1] = a1 | (a1 << 1) | (a1 << 2) | (a1 >> 1) | (a1 >> 2)
                      | (a0 >> 31) | (a0 >> 30) | (a2 << 31) | (a2 << 30);
        ryz[yo][x][2] = a2 | (a2 << 1) | (a2 << 2) | (a2 >> 1) | (a2 >> 2)
                      | (a1 >> 31) | (a1 >> 30);
    }
    __syncthreads();
    int p = (b * XX + x) * XX + (y0 + yo);
    float4* out = (float4*)(mask + (size_t)p * XX);
#pragma unroll
    for (int k = 0; k < 3; k++) {
        unsigned a = ryz[yo][x][k];
#pragma unroll
        for (int dx = -2; dx <= 2; dx++) {
            if (dx == 0) continue;
            int xx = x + dx;
            if (xx >= 0 && xx < XX) a |= ryz[yo][xx][k];
        }
        a |= g_rand[p * 3 + k];
#pragma unroll
        for (int q = 0; q < 8; q++) {
            int sh = q * 4;
            float4 f;
            f.x = (a >> (sh + 0)) & 1u ? 1.0f : 0.0f;
            f.y = (a >> (sh + 1)) & 1u ? 1.0f : 0.0f;
            f.z = (a >> (sh + 2)) & 1u ? 1.0f : 0.0f;
            f.w = (a >> (sh + 3)) & 1u ? 1.0f : 0.0f;
            out[k * 8 + q] = f;
        }
    }
}

extern "C" void kernel_launch(void* const* d_in, const int* in_sizes, int n_in,
                              void* d_out, int out_size) {
    const float* coords = (const float*)d_in[0];
    const float* T      = (const float*)d_in[1];
    const float* Tinv   = (const float*)d_in[2];
    const int*   sparse = (const int*)d_in[3];
    // d_in[4] = conv_w (all-ones 5^3 box; boolean dilation is exact)
    const int*   ridx   = (const int*)d_in[5];

    int npts  = in_sizes[3] / 3;       // B*N
    int nperb = npts / BB;             // N
    int na    = in_sizes[5] / 3;       // NUM_ADD

    float* occ_out  = (float*)d_out;
    float* mask_out = occ_out + (size_t)BB * XYZ;

    int sb = (npts / 4 + 255) / 256;               // scatter blocks
    int rb = (na + 255) / 256;                     // rand blocks

    k_init<<<488, 256>>>(coords, T, Tinv);
    k_scatter<<<sb + rb, 256>>>(sparse, npts, nperb, ridx, na, sb);
    k_sample<<<BB * XYZ / 256, 256>>>(occ_out);
    k_dilate<<<BB * (XX / YS), XX * YS>>>(mask_out);
}

// round 7
// speedup vs baseline: 1.2402x; 1.2402x over previous
#include <cuda_runtime.h>

#define BB 4
#define XX 96
#define XYZ (XX*XX*XX)          // 884736
#define G 192
#define GW (G*G*G/32)           // 221184 words per batch
#define NROW (BB*XX*XX)         // 36864 (b,x,y) rows
#define NPACK (NROW*3)          // packed words

// ---------------- device scratch (no allocations allowed) ----------------
__device__ float g_minvox[BB][3];
__device__ float g_posbase[BB][3];
__device__ float g_voxsize[BB][3];
__device__ float g_sizevox[3];
__device__ __align__(16) unsigned g_occ[BB][GW];   // 3.54 MB occupancy bitmap
__device__ __align__(16) unsigned g_pack[NPACK];   // sampled grid, bit-packed along z
__device__ __align__(16) unsigned g_py[NPACK];     // after y+z dilation
__device__ __align__(16) unsigned g_rand[NPACK];   // rand_idx overlay bits
// per-axis trilinear tables: [b*3+c][i]  (c=0:x premul*1152, c=1:y premul*6, c=2:z raw)
__device__ int g_tA[BB*3][XX];
__device__ int g_tB[BB*3][XX];
__device__ int g_tU[BB*3][XX];

// ---------------- K1: init = clear bitmaps + setup math + tables ----------------
__global__ void k_init(const float* __restrict__ coords,
                       const float* __restrict__ T,
                       const float* __restrict__ Tinv) {
    if (blockIdx.x != 0) {
        // clearing blocks
        int nthr = (gridDim.x - 1) * blockDim.x;
        int t = (blockIdx.x - 1) * blockDim.x + threadIdx.x;
        uint4 z4 = make_uint4(0, 0, 0, 0);
        uint4* o4 = (uint4*)g_occ;
        for (int i = t; i < BB * GW / 4; i += nthr) o4[i] = z4;
        uint4* r4 = (uint4*)g_rand;
        for (int i = t; i < NPACK / 4; i += nthr) r4[i] = z4;
        return;
    }
    // block 0: setup
    if (threadIdx.x == 0) {
        float minl[BB][3], maxl[BB][3];
        for (int b = 0; b < BB; b++)
            for (int c = 0; c < 3; c++) {
                float v0 = coords[(size_t)(b * 3 + c) * XYZ];
                float v1 = coords[(size_t)(b * 3 + c) * XYZ + (XYZ - 1)];
                minl[b][c] = fminf(v0, v1);
                maxl[b][c] = fmaxf(v0, v1);
            }
        float msg[3];
        for (int c = 0; c < 3; c++) {
            float m = -3.402823466e38f;
            for (int b = 0; b < BB; b++)
                m = fmaxf(m, (maxl[b][c] + 0.08f) - minl[b][c]);
            msg[c] = m;
        }
        float mv[BB][3];
        for (int b = 0; b < BB; b++) {
            float mh[4] = {minl[b][0], minl[b][1], minl[b][2], 1.0f};
            for (int i = 0; i < 3; i++) {
                float s = 0.0f;
                for (int j = 0; j < 4; j++) s += Tinv[b * 16 + i * 4 + j] * mh[j];
                float v = fmaxf(floorf(s), 0.0f);
                mv[b][i] = v;
                g_minvox[b][i] = v;
            }
        }
        float sv[3];
        for (int i = 0; i < 3; i++) {
            float m = -3.402823466e38f;
            for (int b = 0; b < BB; b++) {
                float s = 0.0f;
                for (int j = 0; j < 3; j++) s += Tinv[b * 16 + i * 4 + j] * msg[j];
                m = fmaxf(m, s);
            }
            sv[i] = ceilf(m);
            g_sizevox[i] = sv[i];
        }
        for (int b = 0; b < BB; b++) {
            float mh[4] = {mv[b][0], mv[b][1], mv[b][2], 1.0f};
            for (int i = 0; i < 3; i++) {
                float s = 0.0f;
                for (int j = 0; j < 4; j++) s += T[b * 16 + i * 4 + j] * mh[j];
                g_posbase[b][i] = s;
                float e = 0.0f;
                for (int j = 0; j < 3; j++) e += T[b * 16 + i * 4 + j] * sv[j];
                g_voxsize[b][i] = e / sv[i];
            }
        }
    }
    __syncthreads();
    for (int t = threadIdx.x; t < BB * 3 * XX; t += blockDim.x) {
        int i  = t % XX;
        int ch = t / XX;          // b*3+c
        int b  = ch / 3;
        int c  = ch - b * 3;
        float off = coords[(size_t)ch * XYZ];
        float val = (float)i * 0.08f + off;              // bit-exact meshgrid value
        float p  = (val - g_posbase[b][c]) / g_voxsize[b][c] - 0.5f;
        float p0 = floorf(p);
        float f  = p - p0;
        int ip = (int)p0;
        int i0 = min(max(ip, 0), G - 1);
        int i1 = min(max(ip + 1, 0), G - 1);
        int mul = (c == 0) ? 1152 : (c == 1) ? 6 : 1;
        g_tA[ch][i] = i0 * mul;
        g_tB[ch][i] = i1 * mul;
        g_tU[ch][i] = (f > 0.0f) ? 1 : 0;
    }
}

// ---------------- K2: scatter sparse points + rand overlay ----------------
__global__ void k_scatter(const int* __restrict__ sparse, int npts, int nperb,
                          const int* __restrict__ ridx, int na, int sb) {
    if ((int)blockIdx.x >= sb) {
        // rand overlay: bit-scatter into g_rand
        int i = (blockIdx.x - sb) * blockDim.x + threadIdx.x;
        if (i >= na) return;
        int b = i % BB;
        int x = ridx[i];
        int y = ridx[na + i];
        int z = ridx[2 * na + i];
        int p = (b * XX + x) * XX + y;
        atomicOr(&g_rand[p * 3 + (z >> 5)], 1u << (z & 31));
        return;
    }
    int t = blockIdx.x * blockDim.x + threadIdx.x;
    int p0 = t * 4;
    if (p0 >= npts) return;
    const int4* s4 = (const int4*)(sparse + (size_t)p0 * 3);
    int4 a = s4[0], bq = s4[1], cq = s4[2];
    int pts[4][3] = {{a.x, a.y, a.z}, {a.w, bq.x, bq.y},
                     {bq.z, bq.w, cq.x}, {cq.y, cq.z, cq.w}};
    int sv0 = (int)g_sizevox[0], sv1 = (int)g_sizevox[1], sv2 = (int)g_sizevox[2];
    int b = p0 / nperb;   // nperb % 4 == 0 -> all 4 points same batch
    int m0 = (int)g_minvox[b][0], m1 = (int)g_minvox[b][1], m2 = (int)g_minvox[b][2];
    unsigned* occ = g_occ[b];
#pragma unroll
    for (int i = 0; i < 4; i++) {
        if (p0 + i >= npts) return;
        int se0 = pts[i][0] - m0;
        int se1 = pts[i][1] - m1;
        int se2 = pts[i][2] - m2;
        if (se0 < 0 || se0 >= sv0 || se1 < 0 || se1 >= sv1 || se2 < 0 || se2 >= sv2)
            continue;
        int id = (min(se0, G - 1) * G + min(se1, G - 1)) * G + min(se2, G - 1);
        atomicOr(&occ[id >> 5], 1u << (id & 31));
    }
}

// ---------------- K3: table-driven boolean trilinear sample ----------------
__global__ void k_sample(float* __restrict__ occ_out) {
    int v = blockIdx.x * blockDim.x + threadIdx.x;   // grid sized exactly BB*XYZ
    int b = v / XYZ;
    int r = v - b * XYZ;
    int z = r % XX;
    int y = (r / XX) % XX;
    int x = r / (XX * XX);
    int bc = b * 3;
    int wx0 = g_tA[bc][x],     wx1 = g_tB[bc][x];     bool ux = g_tU[bc][x];
    int wy0 = g_tA[bc + 1][y], wy1 = g_tB[bc + 1][y]; bool uy = g_tU[bc + 1][y];
    int iz0 = g_tA[bc + 2][z], iz1 = g_tB[bc + 2][z]; bool uz = g_tU[bc + 2][z];
    const unsigned* occ = g_occ[b];
    int zw0 = iz0 >> 5; unsigned mz0 = 1u << (iz0 & 31);
    int zw1 = iz1 >> 5; unsigned mz1 = 1u << (iz1 & 31);
    bool samew = (zw1 == zw0);
    unsigned acc = 0;
#define PROBE(base) do {                                             \
        unsigned w0 = occ[(base) + zw0];                             \
        acc |= w0 & mz0;                                             \
        if (uz) {                                                    \
            unsigned w1 = samew ? w0 : occ[(base) + zw1];            \
            acc |= w1 & mz1;                                         \
        }                                                            \
    } while (0)
    PROBE(wx0 + wy0);
    if (uy) PROBE(wx0 + wy1);
    if (ux) {
        PROBE(wx1 + wy0);
        if (uy) PROBE(wx1 + wy1);
    }
#undef PROBE
    bool any = acc != 0;
    occ_out[v] = any ? 1.0f : 0.0f;
    unsigned w = __ballot_sync(0xFFFFFFFFu, any);
    if ((v & 31) == 0) g_pack[v >> 5] = w;
}

// ---------------- K4a: y-OR + z-bitshift dilation (per row) ----------------
__global__ void k_dilate_yz() {
    int p = blockIdx.x * blockDim.x + threadIdx.x;
    if (p >= NROW) return;
    int y  = p % XX;
    int xr = p / XX;                  // b*XX + x
    unsigned a0 = 0, a1 = 0, a2 = 0;
#pragma unroll
    for (int dy = -2; dy <= 2; dy++) {
        int yy = y + dy;
        if (yy < 0 || yy >= XX) continue;
        const unsigned* q = &g_pack[(xr * XX + yy) * 3];
        a0 |= q[0]; a1 |= q[1]; a2 |= q[2];
    }
    unsigned r0 = a0 | (a0 << 1) | (a0 << 2) | (a0 >> 1) | (a0 >> 2)
                | (a1 << 31) | (a1 << 30);
    unsigned r1 = a1 | (a1 << 1) | (a1 << 2) | (a1 >> 1) | (a1 >> 2)
                | (a0 >> 31) | (a0 >> 30) | (a2 << 31) | (a2 << 30);
    unsigned r2 = a2 | (a2 << 1) | (a2 << 2) | (a2 >> 1) | (a2 >> 2)
                | (a1 >> 31) | (a1 >> 30);
    unsigned* o = &g_py[p * 3];
    o[0] = r0; o[1] = r1; o[2] = r2;
}

// ---------------- K4b: x-OR + rand overlay + float expand (per word) ----------------
__global__ void k_dilate_x(float* __restrict__ mask) {
    int w = blockIdx.x * blockDim.x + threadIdx.x;
    if (w >= NPACK) return;
    int k = w % 3;
    int p = w / 3;                    // (b,x,y) row
    int y = p % XX;
    int x = (p / XX) % XX;
    int b = p / (XX * XX);
    unsigned a = g_rand[w];
#pragma unroll
    for (int dx = -2; dx <= 2; dx++) {
        int xx = x + dx;
        if (xx < 0 || xx >= XX) continue;
        a |= g_py[(((b * XX + xx) * XX) + y) * 3 + k];
    }
    float4* out = (float4*)(mask + (size_t)p * XX + k * 32);
#pragma unroll
    for (int q = 0; q < 8; q++) {
        int sh = q * 4;
        float4 f;
        f.x = (a >> (sh + 0)) & 1u ? 1.0f : 0.0f;
        f.y = (a >> (sh + 1)) & 1u ? 1.0f : 0.0f;
        f.z = (a >> (sh + 2)) & 1u ? 1.0f : 0.0f;
        f.w = (a >> (sh + 3)) & 1u ? 1.0f : 0.0f;
        out[q] = f;
    }
}

extern "C" void kernel_launch(void* const* d_in, const int* in_sizes, int n_in,
                              void* d_out, int out_size) {
    const float* coords = (const float*)d_in[0];
    const float* T      = (const float*)d_in[1];
    const float* Tinv   = (const float*)d_in[2];
    const int*   sparse = (const int*)d_in[3];
    // d_in[4] = conv_w (all-ones 5^3 box; boolean dilation is exact)
    const int*   ridx   = (const int*)d_in[5];

    int npts  = in_sizes[3] / 3;       // B*N
    int nperb = npts / BB;             // N
    int na    = in_sizes[5] / 3;       // NUM_ADD

    float* occ_out  = (float*)d_out;
    float* mask_out = occ_out + (size_t)BB * XYZ;

    int sb = (npts / 4 + 255) / 256;               // scatter blocks
    int rb = (na + 255) / 256;                     // rand blocks

    k_init<<<488, 256>>>(coords, T, Tinv);
    k_scatter<<<sb + rb, 256>>>(sparse, npts, nperb, ridx, na, sb);
    k_sample<<<BB * XYZ / 256, 256>>>(occ_out);
    k_dilate_yz<<<(NROW + 127) / 128, 128>>>();
    k_dilate_x<<<(NPACK + 255) / 256, 256>>>(mask_out);
}

// round 8
// speedup vs baseline: 1.3128x; 1.0585x over previous
#include <cuda_runtime.h>

#define BB 4
#define XX 96
#define XYZ (XX*XX*XX)          // 884736
#define G 192
#define GW (G*G*G/32)           // 221184 words per batch
#define NROW (BB*XX*XX)         // 36864 (b,x,y) rows
#define NPACK (NROW*3)          // packed words

// ---------------- device scratch (no allocations allowed) ----------------
__device__ float g_minvox[BB][3];
__device__ float g_posbase[BB][3];
__device__ float g_voxsize[BB][3];
__device__ float g_sizevox[3];
__device__ __align__(16) unsigned g_occ[BB][GW];   // 3.54 MB occupancy bitmap
__device__ __align__(16) unsigned g_pack[NPACK];   // sampled grid, bit-packed along z
__device__ __align__(16) unsigned g_py[NPACK];     // after y+z dilation
__device__ __align__(16) unsigned g_rand[NPACK];   // rand_idx overlay bits
// per-axis trilinear tables: [b*3+c][i]  (c=0:x premul*1152, c=1:y premul*6, c=2:z raw)
__device__ int g_tA[BB*3][XX];
__device__ int g_tB[BB*3][XX];
__device__ int g_tU[BB*3][XX];

// ---------------- K1: init = clear bitmaps + setup math + tables ----------------
__global__ void k_init(const float* __restrict__ coords,
                       const float* __restrict__ T,
                       const float* __restrict__ Tinv) {
    if (blockIdx.x != 0) {
        // clearing blocks
        int nthr = (gridDim.x - 1) * blockDim.x;
        int t = (blockIdx.x - 1) * blockDim.x + threadIdx.x;
        uint4 z4 = make_uint4(0, 0, 0, 0);
        uint4* o4 = (uint4*)g_occ;
        for (int i = t; i < BB * GW / 4; i += nthr) o4[i] = z4;
        uint4* r4 = (uint4*)g_rand;
        for (int i = t; i < NPACK / 4; i += nthr) r4[i] = z4;
        return;
    }
    // block 0: parallel-load inputs into smem, then ALU-only setup
    __shared__ float s_off[BB * 3];      // coords[ch][0]  (raw endpoint 0)
    __shared__ float s_hi[BB * 3];       // coords[ch][XYZ-1]
    __shared__ float s_T[BB * 16];
    __shared__ float s_Ti[BB * 16];
    __shared__ float s_posbase[BB][3];
    __shared__ float s_voxsize[BB][3];
    int tid = threadIdx.x;
    if (tid < BB * 3) {
        s_off[tid] = coords[(size_t)tid * XYZ];
        s_hi[tid]  = coords[(size_t)tid * XYZ + (XYZ - 1)];
    }
    if (tid < BB * 16) {
        s_T[tid]  = T[tid];
        s_Ti[tid] = Tinv[tid];
    }
    __syncthreads();
    if (tid == 0) {
        float minl[BB][3], maxl[BB][3];
        for (int b = 0; b < BB; b++)
            for (int c = 0; c < 3; c++) {
                float v0 = s_off[b * 3 + c], v1 = s_hi[b * 3 + c];
                minl[b][c] = fminf(v0, v1);
                maxl[b][c] = fmaxf(v0, v1);
            }
        float msg[3];
        for (int c = 0; c < 3; c++) {
            float m = -3.402823466e38f;
            for (int b = 0; b < BB; b++)
                m = fmaxf(m, (maxl[b][c] + 0.08f) - minl[b][c]);
            msg[c] = m;
        }
        float mv[BB][3];
        for (int b = 0; b < BB; b++) {
            float mh[4] = {minl[b][0], minl[b][1], minl[b][2], 1.0f};
            for (int i = 0; i < 3; i++) {
                float s = 0.0f;
                for (int j = 0; j < 4; j++) s += s_Ti[b * 16 + i * 4 + j] * mh[j];
                float v = fmaxf(floorf(s), 0.0f);
                mv[b][i] = v;
                g_minvox[b][i] = v;
            }
        }
        float sv[3];
        for (int i = 0; i < 3; i++) {
            float m = -3.402823466e38f;
            for (int b = 0; b < BB; b++) {
                float s = 0.0f;
                for (int j = 0; j < 3; j++) s += s_Ti[b * 16 + i * 4 + j] * msg[j];
                m = fmaxf(m, s);
            }
            sv[i] = ceilf(m);
            g_sizevox[i] = sv[i];
        }
        for (int b = 0; b < BB; b++) {
            float mh[4] = {mv[b][0], mv[b][1], mv[b][2], 1.0f};
            for (int i = 0; i < 3; i++) {
                float s = 0.0f;
                for (int j = 0; j < 4; j++) s += s_T[b * 16 + i * 4 + j] * mh[j];
                s_posbase[b][i] = s;
                g_posbase[b][i] = s;
                float e = 0.0f;
                for (int j = 0; j < 3; j++) e += s_T[b * 16 + i * 4 + j] * sv[j];
                float vsz = e / sv[i];
                s_voxsize[b][i] = vsz;
                g_voxsize[b][i] = vsz;
            }
        }
    }
    __syncthreads();
    // per-axis tables: 12 channels x 96 entries, ALU only (smem params)
    for (int t = tid; t < BB * 3 * XX; t += blockDim.x) {
        int i  = t % XX;
        int ch = t / XX;          // b*3+c
        int b  = ch / 3;
        int c  = ch - b * 3;
        float val = (float)i * 0.08f + s_off[ch];        // bit-exact meshgrid value
        float p  = (val - s_posbase[b][c]) / s_voxsize[b][c] - 0.5f;
        float p0 = floorf(p);
        float f  = p - p0;
        int ip = (int)p0;
        int i0 = min(max(ip, 0), G - 1);
        int i1 = min(max(ip + 1, 0), G - 1);
        int mul = (c == 0) ? 1152 : (c == 1) ? 6 : 1;
        g_tA[ch][i] = i0 * mul;
        g_tB[ch][i] = i1 * mul;
        g_tU[ch][i] = (f > 0.0f) ? 1 : 0;
    }
}

// ---------------- K2: scatter sparse points + rand overlay ----------------
__global__ void k_scatter(const int* __restrict__ sparse, int npts, int nperb,
                          const int* __restrict__ ridx, int na, int sb) {
    if ((int)blockIdx.x >= sb) {
        // rand overlay: bit-scatter into g_rand
        int i = (blockIdx.x - sb) * blockDim.x + threadIdx.x;
        if (i >= na) return;
        int b = i % BB;
        int x = ridx[i];
        int y = ridx[na + i];
        int z = ridx[2 * na + i];
        int p = (b * XX + x) * XX + y;
        atomicOr(&g_rand[p * 3 + (z >> 5)], 1u << (z & 31));
        return;
    }
    int t = blockIdx.x * blockDim.x + threadIdx.x;
    int p0 = t * 4;
    if (p0 >= npts) return;
    const int4* s4 = (const int4*)(sparse + (size_t)p0 * 3);
    int4 a = s4[0], bq = s4[1], cq = s4[2];
    int pts[4][3] = {{a.x, a.y, a.z}, {a.w, bq.x, bq.y},
                     {bq.z, bq.w, cq.x}, {cq.y, cq.z, cq.w}};
    int sv0 = (int)g_sizevox[0], sv1 = (int)g_sizevox[1], sv2 = (int)g_sizevox[2];
    int b = p0 / nperb;   // nperb % 4 == 0 -> all 4 points same batch
    int m0 = (int)g_minvox[b][0], m1 = (int)g_minvox[b][1], m2 = (int)g_minvox[b][2];
    unsigned* occ = g_occ[b];
#pragma unroll
    for (int i = 0; i < 4; i++) {
        if (p0 + i >= npts) return;
        int se0 = pts[i][0] - m0;
        int se1 = pts[i][1] - m1;
        int se2 = pts[i][2] - m2;
        if (se0 < 0 || se0 >= sv0 || se1 < 0 || se1 >= sv1 || se2 < 0 || se2 >= sv2)
            continue;
        int id = (min(se0, G - 1) * G + min(se1, G - 1)) * G + min(se2, G - 1);
        atomicOr(&occ[id >> 5], 1u << (id & 31));
    }
}

// ---------------- K3: table-driven boolean trilinear sample ----------------
__global__ void k_sample(float* __restrict__ occ_out) {
    int v = blockIdx.x * blockDim.x + threadIdx.x;   // grid sized exactly BB*XYZ
    int b = v / XYZ;
    int r = v - b * XYZ;
    int z = r % XX;
    int y = (r / XX) % XX;
    int x = r / (XX * XX);
    int bc = b * 3;
    int wx0 = g_tA[bc][x],     wx1 = g_tB[bc][x];     bool ux = g_tU[bc][x];
    int wy0 = g_tA[bc + 1][y], wy1 = g_tB[bc + 1][y]; bool uy = g_tU[bc + 1][y];
    int iz0 = g_tA[bc + 2][z], iz1 = g_tB[bc + 2][z]; bool uz = g_tU[bc + 2][z];
    const unsigned* occ = g_occ[b];
    int zw0 = iz0 >> 5; unsigned mz0 = 1u << (iz0 & 31);
    int zw1 = iz1 >> 5; unsigned mz1 = 1u << (iz1 & 31);
    bool samew = (zw1 == zw0);
    unsigned acc = 0;
#define PROBE(base) do {                                             \
        unsigned w0 = occ[(base) + zw0];                             \
        acc |= w0 & mz0;                                             \
        if (uz) {                                                    \
            unsigned w1 = samew ? w0 : occ[(base) + zw1];            \
            acc |= w1 & mz1;                                         \
        }                                                            \
    } while (0)
    PROBE(wx0 + wy0);
    if (uy) PROBE(wx0 + wy1);
    if (ux) {
        PROBE(wx1 + wy0);
        if (uy) PROBE(wx1 + wy1);
    }
#undef PROBE
    bool any = acc != 0;
    occ_out[v] = any ? 1.0f : 0.0f;
    unsigned w = __ballot_sync(0xFFFFFFFFu, any);
    if ((v & 31) == 0) g_pack[v >> 5] = w;
}

// ---------------- K4a: y-OR + z-bitshift dilation (per WORD, branchless) ----------------
__global__ void k_dilate_yz() {
    int w = blockIdx.x * blockDim.x + threadIdx.x;
    if (w >= NPACK) return;
    int k = w % 3;
    int p = w / 3;                    // (b,x,y) row
    int y  = p % XX;
    int xr = p / XX;                  // b*XX + x
    unsigned ac = 0, am = 0, ap = 0;  // own word, k-1, k+1 (y-OR accumulators)
    bool hm = (k > 0), hp = (k < 2);
#pragma unroll
    for (int dy = -2; dy <= 2; dy++) {
        int yy = y + dy;
        if (yy < 0 || yy >= XX) continue;
        const unsigned* q = &g_pack[((xr * XX) + yy) * 3 + k];
        ac |= q[0];
        if (hm) am |= q[-1];
        if (hp) ap |= q[1];
    }
    unsigned r = ac | (ac << 1) | (ac << 2) | (ac >> 1) | (ac >> 2)
               | (ap << 31) | (ap << 30)      // low bits of next word
               | (am >> 31) | (am >> 30);     // high bits of prev word
    g_py[w] = r;
}

// ---------------- K4b: x-OR + rand overlay + float expand (per word) ----------------
__global__ void k_dilate_x(float* __restrict__ mask) {
    int w = blockIdx.x * blockDim.x + threadIdx.x;
    if (w >= NPACK) return;
    int k = w % 3;
    int p = w / 3;                    // (b,x,y) row
    int y = p % XX;
    int x = (p / XX) % XX;
    int b = p / (XX * XX);
    unsigned a = g_rand[w];
#pragma unroll
    for (int dx = -2; dx <= 2; dx++) {
        int xx = x + dx;
        if (xx < 0 || xx >= XX) continue;
        a |= g_py[(((b * XX + xx) * XX) + y) * 3 + k];
    }
    float4* out = (float4*)(mask + (size_t)p * XX + k * 32);
#pragma unroll
    for (int q = 0; q < 8; q++) {
        int sh = q * 4;
        float4 f;
        f.x = (a >> (sh + 0)) & 1u ? 1.0f : 0.0f;
        f.y = (a >> (sh + 1)) & 1u ? 1.0f : 0.0f;
        f.z = (a >> (sh + 2)) & 1u ? 1.0f : 0.0f;
        f.w = (a >> (sh + 3)) & 1u ? 1.0f : 0.0f;
        out[q] = f;
    }
}

extern "C" void kernel_launch(void* const* d_in, const int* in_sizes, int n_in,
                              void* d_out, int out_size) {
    const float* coords = (const float*)d_in[0];
    const float* T      = (const float*)d_in[1];
    const float* Tinv   = (const float*)d_in[2];
    const int*   sparse = (const int*)d_in[3];
    // d_in[4] = conv_w (all-ones 5^3 box; boolean dilation is exact)
    const int*   ridx   = (const int*)d_in[5];

    int npts  = in_sizes[3] / 3;       // B*N
    int nperb = npts / BB;             // N
    int na    = in_sizes[5] / 3;       // NUM_ADD

    float* occ_out  = (float*)d_out;
    float* mask_out = occ_out + (size_t)BB * XYZ;

    int sb = (npts / 4 + 255) / 256;               // scatter blocks
    int rb = (na + 255) / 256;                     // rand blocks

    k_init<<<488, 256>>>(coords, T, Tinv);
    k_scatter<<<sb + rb, 256>>>(sparse, npts, nperb, ridx, na, sb);
    k_sample<<<BB * XYZ / 256, 256>>>(occ_out);
    k_dilate_yz<<<(NPACK + 255) / 256, 256>>>();
    k_dilate_x<<<(NPACK + 255) / 256, 256>>>(mask_out);
}